// round 16
// baseline (speedup 1.0000x reference)
#include <cuda_runtime.h>
#include <cuda_bf16.h>
#include <math.h>
#include <stdint.h>

// Problem constants
#define BB 4
#define SS 2048
#define DD 1024
#define HH 16
#define DKK 64
#define MM (BB * SS)   // 8192
#define GK 1024

// ---------------- scratch (device globals; no runtime alloc allowed) --------
__device__ float g_qp[(size_t)MM * DD];
__device__ float g_kp[(size_t)MM * DD];
__device__ float g_vp[(size_t)MM * DD];
__device__ float g_ao[(size_t)MM * DD];
__device__ float g_qc[(size_t)MM * DD];      // tf32-rounded inputs
__device__ float g_kc[(size_t)MM * DD];
__device__ float g_vc[(size_t)MM * DD];
__device__ float g_wc[4][(size_t)DD * DD];   // tf32-rounded weights

// ==================== helpers ================================================
__device__ __forceinline__ uint32_t f2tf32(float x) {
    uint32_t u;
    asm("cvt.rna.tf32.f32 %0, %1;" : "=r"(u) : "f"(x));
    return u;
}

__device__ __forceinline__ uint32_t smem_u32(const void* p) {
    uint32_t a;
    asm("{ .reg .u64 t; cvta.to.shared.u64 t, %1; cvt.u32.u64 %0, t; }"
        : "=r"(a) : "l"(p));
    return a;
}

__device__ __forceinline__ void cp_async16(uint32_t dst, const void* src) {
    asm volatile("cp.async.ca.shared.global [%0], [%1], 16;"
                 :: "r"(dst), "l"(src));
}
#define CP_COMMIT() asm volatile("cp.async.commit_group;" ::: "memory")
#define CP_WAIT(N)  asm volatile("cp.async.wait_group %0;" :: "n"(N) : "memory")

// m16n8k8 tf32 mma
__device__ __forceinline__ void mma_tf32(float* c, const uint32_t* a,
                                         const uint32_t* b) {
    asm volatile(
        "mma.sync.aligned.m16n8k8.row.col.f32.tf32.tf32.f32 "
        "{%0,%1,%2,%3}, {%4,%5,%6,%7}, {%8,%9}, {%0,%1,%2,%3};"
        : "+f"(c[0]), "+f"(c[1]), "+f"(c[2]), "+f"(c[3])
        : "r"(a[0]), "r"(a[1]), "r"(a[2]), "r"(a[3]), "r"(b[0]), "r"(b[1]));
}

// ==================== fused tf32 pre-rounding passes =========================
__global__ void __launch_bounds__(256)
cvt3_tf32(const float* __restrict__ s0, const float* __restrict__ s1,
          const float* __restrict__ s2, float* __restrict__ d0,
          float* __restrict__ d1, float* __restrict__ d2, int n4) {
    const int z = blockIdx.z;
    const float* s = (z == 0) ? s0 : (z == 1) ? s1 : s2;
    float* d = (z == 0) ? d0 : (z == 1) ? d1 : d2;
    int i = blockIdx.x * 256 + threadIdx.x;
    if (i < n4) {
        float4 v = *(const float4*)(s + (size_t)i * 4);
        uint4 o;
        o.x = f2tf32(v.x); o.y = f2tf32(v.y);
        o.z = f2tf32(v.z); o.w = f2tf32(v.w);
        *(uint4*)(d + (size_t)i * 4) = o;
    }
}

__global__ void __launch_bounds__(256)
cvt4_tf32(const float* __restrict__ s0, const float* __restrict__ s1,
          const float* __restrict__ s2, const float* __restrict__ s3,
          float* __restrict__ dbase, int n4) {
    const int z = blockIdx.z;
    const float* s = (z == 0) ? s0 : (z == 1) ? s1 : (z == 2) ? s2 : s3;
    float* d = dbase + (size_t)z * DD * DD;
    int i = blockIdx.x * 256 + threadIdx.x;
    if (i < n4) {
        float4 v = *(const float4*)(s + (size_t)i * 4);
        uint4 o;
        o.x = f2tf32(v.x); o.y = f2tf32(v.y);
        o.z = f2tf32(v.z); o.w = f2tf32(v.w);
        *(uint4*)(d + (size_t)i * 4) = o;
    }
}

// ==================== GEMM core: GKC=64 (half the barriers of R11) ==========
// CTA 128x256, 8 warps as 2(M)x4(N), warp tile 64x64, 2-stage cp.async.
// Stage = A(128x64) + B(64x256) = 100KB; double-buffered 200KB, 1 CTA/SM.
#define GTM 128
#define GTN 256
#define GKC 64
#define ALD 68     // 64 + 4 pad: a-frag banks (4*gid+tg) unique
#define BLD 264    // 256 + 8 pad: b-frag banks (8*tg+gid) unique
#define ABUF (GTM * ALD)     // 8704 floats
#define BBUF (GKC * BLD)     // 16896 floats
#define GSM_FLOATS (2 * (ABUF + BBUF))   // 51200 floats = 204800 B
#define GNC (GK / GKC)       // 16 chunks

__device__ __forceinline__ void gemm_body(
    const float* __restrict__ A, const float* __restrict__ W,
    const float* __restrict__ bias, float* __restrict__ C,
    float oscale, int oround, uint32_t* gsm) {
    const uint32_t sb = smem_u32(gsm);

    const int tid = threadIdx.x;
    const int wid = tid >> 5, lane = tid & 31;
    const int gid = lane >> 2, tg = lane & 3;
    const int bm = blockIdx.y * GTM, bn = blockIdx.x * GTN;
    const int wm = (wid >> 2) * 64;
    const int wn = (wid & 3) * 64;

    float acc[4][8][4];
#pragma unroll
    for (int mt = 0; mt < 4; mt++)
#pragma unroll
        for (int nt = 0; nt < 8; nt++)
#pragma unroll
            for (int c = 0; c < 4; c++) acc[mt][nt][c] = 0.0f;

    auto issue = [&](int kc, int buf) {
        // A tile: 128 rows x 64 floats = 2048 x 16B (8 per thread)
#pragma unroll
        for (int t = 0; t < 8; t++) {
            const int i = tid + t * 256;
            const int r = i >> 4, c16 = i & 15;
            cp_async16(sb + (uint32_t)(buf * ABUF + r * ALD + c16 * 4) * 4u,
                       A + (size_t)(bm + r) * GK + kc * GKC + c16 * 4);
        }
        // B tile: 64 rows x 256 floats = 4096 x 16B (16 per thread)
#pragma unroll
        for (int t = 0; t < 16; t++) {
            const int i = tid + t * 256;
            const int r = i >> 6, c16 = i & 63;
            cp_async16(sb + (uint32_t)(2 * ABUF + buf * BBUF + r * BLD + c16 * 4) * 4u,
                       W + (size_t)(kc * GKC + r) * DD + bn + c16 * 4);
        }
        CP_COMMIT();
    };

    auto compute = [&](int buf) {
        const uint32_t* As = gsm + buf * ABUF;
        const uint32_t* Bs = gsm + 2 * ABUF + buf * BBUF;
#pragma unroll
        for (int ks = 0; ks < 8; ks++) {
            const int k0 = ks * 8;
            uint32_t af[4][4], bf[8][2];
#pragma unroll
            for (int mt = 0; mt < 4; mt++) {
                const uint32_t* p = As + (wm + mt * 16 + gid) * ALD + k0 + tg;
                af[mt][0] = p[0];
                af[mt][1] = p[8 * ALD];
                af[mt][2] = p[4];
                af[mt][3] = p[8 * ALD + 4];
            }
#pragma unroll
            for (int nt = 0; nt < 8; nt++) {
                const uint32_t* p = Bs + (k0 + tg) * BLD + wn + nt * 8 + gid;
                bf[nt][0] = p[0];
                bf[nt][1] = p[4 * BLD];
            }
#pragma unroll
            for (int mt = 0; mt < 4; mt++)
#pragma unroll
                for (int nt = 0; nt < 8; nt++)
                    mma_tf32(acc[mt][nt], af[mt], bf[nt]);
        }
    };

    issue(0, 0);
    for (int kc = 0; kc < GNC; kc++) {
        const int buf = kc & 1;
        CP_WAIT(0);
        __syncthreads();
        if (kc < GNC - 1) issue(kc + 1, buf ^ 1);
        compute(buf);
    }

    auto finish = [&](float x) -> float {
        float v = x * oscale;
        if (oround) v = __uint_as_float(f2tf32(v));
        return v;
    };

#pragma unroll
    for (int mt = 0; mt < 4; mt++) {
        const int row = bm + wm + mt * 16 + gid;
#pragma unroll
        for (int nt = 0; nt < 8; nt++) {
            const int col = bn + wn + nt * 8 + 2 * tg;
            const float b0 = __ldg(bias + col), b1 = __ldg(bias + col + 1);
            float2 v0 = make_float2(finish(acc[mt][nt][0] + b0),
                                    finish(acc[mt][nt][1] + b1));
            float2 v1 = make_float2(finish(acc[mt][nt][2] + b0),
                                    finish(acc[mt][nt][3] + b1));
            *(float2*)(C + (size_t)row * DD + col) = v0;
            *(float2*)(C + (size_t)(row + 8) * DD + col) = v1;
        }
    }
}

__global__ void __launch_bounds__(256, 1)
gemm_qkv(const float* __restrict__ A0, const float* __restrict__ A1,
         const float* __restrict__ A2, const float* __restrict__ Wbase,
         const float* __restrict__ b0, const float* __restrict__ b1,
         const float* __restrict__ b2, float* __restrict__ C0,
         float* __restrict__ C1, float* __restrict__ C2, float qscale) {
    extern __shared__ __align__(16) uint32_t gsm[];
    const int z = blockIdx.z;
    const float* A = (z == 0) ? A0 : (z == 1) ? A1 : A2;
    const float* W = Wbase + (size_t)z * DD * DD;
    const float* bias = (z == 0) ? b0 : (z == 1) ? b1 : b2;
    float* C = (z == 0) ? C0 : (z == 1) ? C1 : C2;
    const float oscale = (z == 0) ? qscale : 1.0f;
    gemm_body(A, W, bias, C, oscale, 1, gsm);
}

__global__ void __launch_bounds__(256, 1)
gemm_mma(const float* __restrict__ A, const float* __restrict__ W,
         const float* __restrict__ bias, float* __restrict__ C,
         float oscale, int oround) {
    extern __shared__ __align__(16) uint32_t gsm[];
    gemm_body(A, W, bias, C, oscale, oround, gsm);
}

// ==================== Flash attention on mma.sync tf32 ======================
// FROZEN R11 config (best measured: 463.8us). Do not modify.
#define FBQ 128
#define FQLD 68
#define FVLD 72
#define KS_OFF (FBQ * FQLD)
#define VS_OFF (KS_OFF + 64 * FQLD)
#define PS_OFF (VS_OFF + 64 * FVLD)
#define FSM_FLOATS (PS_OFF + FBQ * FQLD)   // 105472 B

__global__ void __launch_bounds__(128)
flash_mma(const float* __restrict__ Qp, const float* __restrict__ Kp,
          const float* __restrict__ Vp, float* __restrict__ Op) {
    extern __shared__ __align__(16) uint32_t fsm[];
    uint32_t* Qs = fsm;
    uint32_t* Ks = fsm + KS_OFF;
    uint32_t* Vs = fsm + VS_OFF;
    uint32_t* Ps = fsm + PS_OFF;
    const uint32_t sb = smem_u32(fsm);

    const int tid = threadIdx.x;
    const int wid = tid >> 5, lane = tid & 31;
    const int gid = lane >> 2, tg = lane & 3;
    const int q0 = blockIdx.x * FBQ;
    const int h = blockIdx.y, b = blockIdx.z;
    const size_t base = (size_t)b * SS * DD + (size_t)h * DKK;
    const int wm = wid * 32;

#pragma unroll
    for (int t = 0; t < 16; t++) {
        const int i = tid + t * 128;
        const int r = i >> 4, c = (i & 15) * 4;
        cp_async16(sb + (uint32_t)(r * FQLD + c) * 4u,
                   Qp + base + (size_t)(q0 + r) * DD + c);
    }
    CP_COMMIT();

    float m_i[2][2], l_i[2][2];
    float oacc[2][8][4];
#pragma unroll
    for (int mt = 0; mt < 2; mt++) {
        m_i[mt][0] = -1e30f; m_i[mt][1] = -1e30f;
        l_i[mt][0] = 0.0f;   l_i[mt][1] = 0.0f;
#pragma unroll
        for (int nt = 0; nt < 8; nt++)
#pragma unroll
            for (int c = 0; c < 4; c++) oacc[mt][nt][c] = 0.0f;
    }

    for (int kb = 0; kb < SS / 64; kb++) {
        __syncthreads();
#pragma unroll
        for (int t = 0; t < 8; t++) {
            const int i = tid + t * 128;
            const int r = i >> 4, c = (i & 15) * 4;
            cp_async16(sb + (uint32_t)(KS_OFF + r * FQLD + c) * 4u,
                       Kp + base + (size_t)(kb * 64 + r) * DD + c);
        }
        CP_COMMIT();
#pragma unroll
        for (int t = 0; t < 8; t++) {
            const int i = tid + t * 128;
            const int r = i >> 4, c = (i & 15) * 4;
            cp_async16(sb + (uint32_t)(VS_OFF + r * FVLD + c) * 4u,
                       Vp + base + (size_t)(kb * 64 + r) * DD + c);
        }
        CP_COMMIT();
        CP_WAIT(1);
        __syncthreads();

        float s[2][8][4];
#pragma unroll
        for (int mt = 0; mt < 2; mt++)
#pragma unroll
            for (int nt = 0; nt < 8; nt++)
#pragma unroll
                for (int c = 0; c < 4; c++) s[mt][nt][c] = 0.0f;

#pragma unroll
        for (int ks = 0; ks < 8; ks++) {
            const int k0 = ks * 8;
            uint32_t af[2][4], bf[8][2];
#pragma unroll
            for (int mt = 0; mt < 2; mt++) {
                const uint32_t* ap = Qs + (wm + mt * 16 + gid) * FQLD + k0 + tg;
                af[mt][0] = ap[0];
                af[mt][1] = ap[8 * FQLD];
                af[mt][2] = ap[4];
                af[mt][3] = ap[8 * FQLD + 4];
            }
#pragma unroll
            for (int nt = 0; nt < 8; nt++) {
                const uint32_t* bp = Ks + (nt * 8 + gid) * FQLD + k0 + tg;
                bf[nt][0] = bp[0];
                bf[nt][1] = bp[4];
            }
#pragma unroll
            for (int mt = 0; mt < 2; mt++)
#pragma unroll
                for (int nt = 0; nt < 8; nt++)
                    mma_tf32(s[mt][nt], af[mt], bf[nt]);
        }

#pragma unroll
        for (int mt = 0; mt < 2; mt++) {
            float mx0 = -1e30f, mx1 = -1e30f;
#pragma unroll
            for (int nt = 0; nt < 8; nt++) {
                mx0 = fmaxf(mx0, fmaxf(s[mt][nt][0], s[mt][nt][1]));
                mx1 = fmaxf(mx1, fmaxf(s[mt][nt][2], s[mt][nt][3]));
            }
#pragma unroll
            for (int m = 1; m <= 2; m <<= 1) {
                mx0 = fmaxf(mx0, __shfl_xor_sync(0xffffffffu, mx0, m));
                mx1 = fmaxf(mx1, __shfl_xor_sync(0xffffffffu, mx1, m));
            }
            const float mn0 = fmaxf(m_i[mt][0], mx0);
            const float mn1 = fmaxf(m_i[mt][1], mx1);
            const float corr0 = exp2f(m_i[mt][0] - mn0);
            const float corr1 = exp2f(m_i[mt][1] - mn1);
            float sum0 = 0.0f, sum1 = 0.0f;
#pragma unroll
            for (int nt = 0; nt < 8; nt++) {
                s[mt][nt][0] = exp2f(s[mt][nt][0] - mn0);
                s[mt][nt][1] = exp2f(s[mt][nt][1] - mn0);
                s[mt][nt][2] = exp2f(s[mt][nt][2] - mn1);
                s[mt][nt][3] = exp2f(s[mt][nt][3] - mn1);
                sum0 += s[mt][nt][0] + s[mt][nt][1];
                sum1 += s[mt][nt][2] + s[mt][nt][3];
            }
#pragma unroll
            for (int m = 1; m <= 2; m <<= 1) {
                sum0 += __shfl_xor_sync(0xffffffffu, sum0, m);
                sum1 += __shfl_xor_sync(0xffffffffu, sum1, m);
            }
            l_i[mt][0] = l_i[mt][0] * corr0 + sum0;
            l_i[mt][1] = l_i[mt][1] * corr1 + sum1;
            m_i[mt][0] = mn0;
            m_i[mt][1] = mn1;
#pragma unroll
            for (int nt = 0; nt < 8; nt++) {
                oacc[mt][nt][0] *= corr0; oacc[mt][nt][1] *= corr0;
                oacc[mt][nt][2] *= corr1; oacc[mt][nt][3] *= corr1;
            }

#pragma unroll
            for (int nt = 0; nt < 8; nt++) {
                uint32_t* pp = Ps + (wm + mt * 16 + gid) * FQLD + nt * 8 + 2 * tg;
                uint2 lo = make_uint2(f2tf32(s[mt][nt][0]), f2tf32(s[mt][nt][1]));
                uint2 hi = make_uint2(f2tf32(s[mt][nt][2]), f2tf32(s[mt][nt][3]));
                *(uint2*)pp = lo;
                *(uint2*)(pp + 8 * FQLD) = hi;
            }
        }
        __syncwarp();
        CP_WAIT(0);
        __syncthreads();

#pragma unroll
        for (int ks = 0; ks < 8; ks++) {
            const int k0 = ks * 8;
            uint32_t af[2][4], bf[8][2];
#pragma unroll
            for (int mt = 0; mt < 2; mt++) {
                const uint32_t* ap = Ps + (wm + mt * 16 + gid) * FQLD + k0 + tg;
                af[mt][0] = ap[0];
                af[mt][1] = ap[8 * FQLD];
                af[mt][2] = ap[4];
                af[mt][3] = ap[8 * FQLD + 4];
            }
#pragma unroll
            for (int nt = 0; nt < 8; nt++) {
                const uint32_t* bp = Vs + (k0 + tg) * FVLD + nt * 8 + gid;
                bf[nt][0] = bp[0];
                bf[nt][1] = bp[4 * FVLD];
            }
#pragma unroll
            for (int mt = 0; mt < 2; mt++)
#pragma unroll
                for (int nt = 0; nt < 8; nt++)
                    mma_tf32(oacc[mt][nt], af[mt], bf[nt]);
        }
    }

#pragma unroll
    for (int mt = 0; mt < 2; mt++) {
        const float inv0 = 1.0f / l_i[mt][0];
        const float inv1 = 1.0f / l_i[mt][1];
        const int row = q0 + wm + mt * 16 + gid;
#pragma unroll
        for (int nt = 0; nt < 8; nt++) {
            const int col = nt * 8 + 2 * tg;
            uint2 v0 = make_uint2(f2tf32(oacc[mt][nt][0] * inv0),
                                  f2tf32(oacc[mt][nt][1] * inv0));
            uint2 v1 = make_uint2(f2tf32(oacc[mt][nt][2] * inv1),
                                  f2tf32(oacc[mt][nt][3] * inv1));
            *(uint2*)(Op + base + (size_t)row * DD + col) = v0;
            *(uint2*)(Op + base + (size_t)(row + 8) * DD + col) = v1;
        }
    }
}

// ---------------- launch -----------------------------------------------------
extern "C" void kernel_launch(void* const* d_in, const int* in_sizes, int n_in,
                              void* d_out, int out_size) {
    (void)in_sizes; (void)n_in; (void)out_size;
    const float* q  = (const float*)d_in[0];
    const float* k  = (const float*)d_in[1];
    const float* v  = (const float*)d_in[2];
    const float* Wq = (const float*)d_in[3];
    const float* bq = (const float*)d_in[4];
    const float* Wk = (const float*)d_in[5];
    const float* bk = (const float*)d_in[6];
    const float* Wv = (const float*)d_in[7];
    const float* bv = (const float*)d_in[8];
    const float* Wo = (const float*)d_in[9];
    const float* bo = (const float*)d_in[10];
    float* out = (float*)d_out;

    float *qp, *kp, *vp, *ao, *qc, *kc_, *vc, *wc;
    cudaGetSymbolAddress((void**)&qp, g_qp);
    cudaGetSymbolAddress((void**)&kp, g_kp);
    cudaGetSymbolAddress((void**)&vp, g_vp);
    cudaGetSymbolAddress((void**)&ao, g_ao);
    cudaGetSymbolAddress((void**)&qc, g_qc);
    cudaGetSymbolAddress((void**)&kc_, g_kc);
    cudaGetSymbolAddress((void**)&vc, g_vc);
    cudaGetSymbolAddress((void**)&wc, g_wc);
    float* wco = wc + 3 * (size_t)DD * DD;

    const int gsm_bytes = GSM_FLOATS * 4;   // 204800
    const int fsm_bytes = FSM_FLOATS * 4;   // 105472
    cudaFuncSetAttribute(gemm_qkv, cudaFuncAttributeMaxDynamicSharedMemorySize,
                         gsm_bytes);
    cudaFuncSetAttribute(gemm_mma, cudaFuncAttributeMaxDynamicSharedMemorySize,
                         gsm_bytes);
    cudaFuncSetAttribute(flash_mma, cudaFuncAttributeMaxDynamicSharedMemorySize,
                         fsm_bytes);

    const float qscale = 0.125f * 1.44269504088896340736f;  // 1/sqrt(dk)*log2(e)

    const int nBig = MM * DD / 4;
    const int nW = DD * DD / 4;
    dim3 cvt3_grid((nBig + 255) / 256, 1, 3);
    cvt3_tf32<<<cvt3_grid, 256>>>(q, k, v, qc, kc_, vc, nBig);
    dim3 cvt4_grid((nW + 255) / 256, 1, 4);
    cvt4_tf32<<<cvt4_grid, 256>>>(Wq, Wk, Wv, Wo, wc, nW);

    dim3 qkv_grid(DD / GTN, MM / GTM, 3);   // (4, 64, 3) = 768 CTAs
    gemm_qkv<<<qkv_grid, 256, gsm_bytes>>>(qc, kc_, vc, wc, bq, bk, bv,
                                           qp, kp, vp, qscale);

    dim3 attn_grid(SS / FBQ, HH, BB);       // (16, 16, 4) = 1024 CTAs
    flash_mma<<<attn_grid, 128, fsm_bytes>>>(qp, kp, vp, ao);

    dim3 gemm_grid(DD / GTN, MM / GTM);     // (4, 64) = 256 CTAs
    gemm_mma<<<gemm_grid, 256, gsm_bytes>>>(ao, wco, bo, out, 1.0f, 0);
}

// round 17
// speedup vs baseline: 1.1074x; 1.1074x over previous
#include <cuda_runtime.h>
#include <cuda_bf16.h>
#include <math.h>
#include <stdint.h>

// Problem constants
#define BB 4
#define SS 2048
#define DD 1024
#define HH 16
#define DKK 64
#define MM (BB * SS)   // 8192
#define GK 1024

// ---------------- scratch (device globals; no runtime alloc allowed) --------
__device__ float g_qp[(size_t)MM * DD];
__device__ float g_kp[(size_t)MM * DD];
__device__ float g_vp[(size_t)MM * DD];
__device__ float g_ao[(size_t)MM * DD];
__device__ float g_qc[(size_t)MM * DD];      // tf32-rounded inputs
__device__ float g_kc[(size_t)MM * DD];
__device__ float g_vc[(size_t)MM * DD];
__device__ float g_wT[4][(size_t)DD * DD];   // tf32-rounded TRANSPOSED weights [n][k]

// ==================== helpers ================================================
__device__ __forceinline__ uint32_t f2tf32(float x) {
    uint32_t u;
    asm("cvt.rna.tf32.f32 %0, %1;" : "=r"(u) : "f"(x));
    return u;
}

__device__ __forceinline__ uint32_t smem_u32(const void* p) {
    uint32_t a;
    asm("{ .reg .u64 t; cvta.to.shared.u64 t, %1; cvt.u32.u64 %0, t; }"
        : "=r"(a) : "l"(p));
    return a;
}

__device__ __forceinline__ void cp_async16(uint32_t dst, const void* src) {
    asm volatile("cp.async.ca.shared.global [%0], [%1], 16;"
                 :: "r"(dst), "l"(src));
}
#define CP_COMMIT() asm volatile("cp.async.commit_group;" ::: "memory")
#define CP_WAIT(N)  asm volatile("cp.async.wait_group %0;" :: "n"(N) : "memory")

// m16n8k8 tf32 mma
__device__ __forceinline__ void mma_tf32(float* c, const uint32_t* a,
                                         const uint32_t* b) {
    asm volatile(
        "mma.sync.aligned.m16n8k8.row.col.f32.tf32.tf32.f32 "
        "{%0,%1,%2,%3}, {%4,%5,%6,%7}, {%8,%9}, {%0,%1,%2,%3};"
        : "+f"(c[0]), "+f"(c[1]), "+f"(c[2]), "+f"(c[3])
        : "r"(a[0]), "r"(a[1]), "r"(a[2]), "r"(a[3]), "r"(b[0]), "r"(b[1]));
}

// ldmatrix x4: one instr loads 4 8x8-b16 matrices (= 4 tf32 fragments)
__device__ __forceinline__ void ldsm_x4(uint32_t* r, uint32_t addr) {
    asm volatile(
        "ldmatrix.sync.aligned.m8n8.x4.shared.b16 {%0,%1,%2,%3}, [%4];"
        : "=r"(r[0]), "=r"(r[1]), "=r"(r[2]), "=r"(r[3]) : "r"(addr));
}

// ==================== fused tf32 pre-rounding passes =========================
__global__ void __launch_bounds__(256)
cvt3_tf32(const float* __restrict__ s0, const float* __restrict__ s1,
          const float* __restrict__ s2, float* __restrict__ d0,
          float* __restrict__ d1, float* __restrict__ d2, int n4) {
    const int z = blockIdx.z;
    const float* s = (z == 0) ? s0 : (z == 1) ? s1 : s2;
    float* d = (z == 0) ? d0 : (z == 1) ? d1 : d2;
    int i = blockIdx.x * 256 + threadIdx.x;
    if (i < n4) {
        float4 v = *(const float4*)(s + (size_t)i * 4);
        uint4 o;
        o.x = f2tf32(v.x); o.y = f2tf32(v.y);
        o.z = f2tf32(v.z); o.w = f2tf32(v.w);
        *(uint4*)(d + (size_t)i * 4) = o;
    }
}

// round + TRANSPOSE weights: wT[n][k] = round(W[k][n])
__global__ void __launch_bounds__(256)
cvt4t_tf32(const float* __restrict__ s0, const float* __restrict__ s1,
           const float* __restrict__ s2, const float* __restrict__ s3,
           float* __restrict__ dbase) {
    __shared__ float t[32][33];
    const int z = blockIdx.z;
    const float* s = (z == 0) ? s0 : (z == 1) ? s1 : (z == 2) ? s2 : s3;
    float* d = dbase + (size_t)z * DD * DD;
    const int bn = blockIdx.x * 32;   // n tile (col of W)
    const int bk = blockIdx.y * 32;   // k tile (row of W)
    const int tx = threadIdx.x, ty = threadIdx.y;
#pragma unroll
    for (int i = ty; i < 32; i += 8)
        t[i][tx] = s[(size_t)(bk + i) * DD + bn + tx];
    __syncthreads();
#pragma unroll
    for (int i = ty; i < 32; i += 8)
        d[(size_t)(bn + i) * DD + bk + tx] =
            __uint_as_float(f2tf32(t[tx][i]));
}

// ==================== GEMM core: ldmatrix-fed fragments ======================
// CTA 128x256, 8 warps as 2(M)x4(N), warp tile 64x64, GKC=32, 2-stage.
// A k-major [m][k]; B = wT n-major [n][k]. Per k-step per warp:
// 4 ldmatrix.x4 (A) + 4 ldmatrix.x4 (B, 2 n-groups each) = 8 instr vs 32 LDS.
#define GTM 128
#define GTN 256
#define GKC 32
#define ALD 36
#define BLD 36
#define ABUF (GTM * ALD)     // 4608 floats
#define BBUF (GTN * BLD)     // 9216 floats
#define GSM_FLOATS (2 * (ABUF + BBUF))   // 27648 floats = 110592 B
#define GNC (GK / GKC)       // 32 chunks

__device__ __forceinline__ void gemm_body(
    const float* __restrict__ A, const float* __restrict__ Wt,
    const float* __restrict__ bias, float* __restrict__ C,
    float oscale, int oround, uint32_t* gsm) {
    const uint32_t sb = smem_u32(gsm);

    const int tid = threadIdx.x;
    const int wid = tid >> 5, lane = tid & 31;
    const int gid = lane >> 2, tg = lane & 3;
    const int bm = blockIdx.y * GTM, bn = blockIdx.x * GTN;
    const int wm = (wid >> 2) * 64;
    const int wn = (wid & 3) * 64;

    // ldmatrix per-lane row/col selectors
    const int arow = (lane & 7) + ((lane >> 3) & 1) * 8;   // A: m0 r0-7,k0; m1 r8-15,k0; m2 r0-7,k4; m3 r8-15,k4
    const int acol = ((lane >> 4) & 1) * 4;
    const int brow = (lane & 7) + ((lane >> 4) & 1) * 8;   // B: m0 n0-7,k0; m1 n0-7,k4; m2 n8-15,k0; m3 n8-15,k4
    const int bcol = ((lane >> 3) & 1) * 4;

    float acc[4][8][4];
#pragma unroll
    for (int mt = 0; mt < 4; mt++)
#pragma unroll
        for (int nt = 0; nt < 8; nt++)
#pragma unroll
            for (int c = 0; c < 4; c++) acc[mt][nt][c] = 0.0f;

    auto issue = [&](int kc, int buf) {
        // A tile: 128 rows x 32 floats = 1024 x 16B (4 per thread)
#pragma unroll
        for (int t = 0; t < 4; t++) {
            const int i = tid + t * 256;
            const int r = i >> 3, c16 = i & 7;
            cp_async16(sb + (uint32_t)(buf * ABUF + r * ALD + c16 * 4) * 4u,
                       A + (size_t)(bm + r) * GK + kc * GKC + c16 * 4);
        }
        // B tile: wT rows n in [bn,bn+256) x 32 k = 2048 x 16B (8 per thread)
#pragma unroll
        for (int t = 0; t < 8; t++) {
            const int i = tid + t * 256;
            const int r = i >> 3, c16 = i & 7;
            cp_async16(sb + (uint32_t)(2 * ABUF + buf * BBUF + r * BLD + c16 * 4) * 4u,
                       Wt + (size_t)(bn + r) * GK + kc * GKC + c16 * 4);
        }
        CP_COMMIT();
    };

    auto compute = [&](int buf) {
        const uint32_t aBase = sb + (uint32_t)(buf * ABUF) * 4u;
        const uint32_t bBase = sb + (uint32_t)(2 * ABUF + buf * BBUF) * 4u;
#pragma unroll
        for (int ks = 0; ks < 4; ks++) {
            const int k0 = ks * 8;
            uint32_t af[4][4], bf[8][2];
#pragma unroll
            for (int mt = 0; mt < 4; mt++) {
                ldsm_x4(af[mt],
                        aBase + (uint32_t)((wm + mt * 16 + arow) * ALD
                                           + k0 + acol) * 4u);
            }
#pragma unroll
            for (int p = 0; p < 4; p++) {   // each x4 covers n-groups 2p, 2p+1
                uint32_t r[4];
                ldsm_x4(r, bBase + (uint32_t)((wn + p * 16 + brow) * BLD
                                              + k0 + bcol) * 4u);
                bf[2 * p][0] = r[0]; bf[2 * p][1] = r[1];
                bf[2 * p + 1][0] = r[2]; bf[2 * p + 1][1] = r[3];
            }
#pragma unroll
            for (int mt = 0; mt < 4; mt++)
#pragma unroll
                for (int nt = 0; nt < 8; nt++)
                    mma_tf32(acc[mt][nt], af[mt], bf[nt]);
        }
    };

    issue(0, 0);
    for (int kc = 0; kc < GNC; kc++) {
        const int buf = kc & 1;
        CP_WAIT(0);
        __syncthreads();
        if (kc < GNC - 1) issue(kc + 1, buf ^ 1);
        compute(buf);
    }

    auto finish = [&](float x) -> float {
        float v = x * oscale;
        if (oround) v = __uint_as_float(f2tf32(v));
        return v;
    };

#pragma unroll
    for (int mt = 0; mt < 4; mt++) {
        const int row = bm + wm + mt * 16 + gid;
#pragma unroll
        for (int nt = 0; nt < 8; nt++) {
            const int col = bn + wn + nt * 8 + 2 * tg;
            const float b0 = __ldg(bias + col), b1 = __ldg(bias + col + 1);
            float2 v0 = make_float2(finish(acc[mt][nt][0] + b0),
                                    finish(acc[mt][nt][1] + b1));
            float2 v1 = make_float2(finish(acc[mt][nt][2] + b0),
                                    finish(acc[mt][nt][3] + b1));
            *(float2*)(C + (size_t)row * DD + col) = v0;
            *(float2*)(C + (size_t)(row + 8) * DD + col) = v1;
        }
    }
}

__global__ void __launch_bounds__(256, 1)
gemm_qkv(const float* __restrict__ A0, const float* __restrict__ A1,
         const float* __restrict__ A2, const float* __restrict__ WTbase,
         const float* __restrict__ b0, const float* __restrict__ b1,
         const float* __restrict__ b2, float* __restrict__ C0,
         float* __restrict__ C1, float* __restrict__ C2, float qscale) {
    extern __shared__ __align__(16) uint32_t gsm[];
    const int z = blockIdx.z;
    const float* A = (z == 0) ? A0 : (z == 1) ? A1 : A2;
    const float* Wt = WTbase + (size_t)z * DD * DD;
    const float* bias = (z == 0) ? b0 : (z == 1) ? b1 : b2;
    float* C = (z == 0) ? C0 : (z == 1) ? C1 : C2;
    const float oscale = (z == 0) ? qscale : 1.0f;
    gemm_body(A, Wt, bias, C, oscale, 1, gsm);
}

__global__ void __launch_bounds__(256, 1)
gemm_mma(const float* __restrict__ A, const float* __restrict__ Wt,
         const float* __restrict__ bias, float* __restrict__ C,
         float oscale, int oround) {
    extern __shared__ __align__(16) uint32_t gsm[];
    gemm_body(A, Wt, bias, C, oscale, oround, gsm);
}

// ==================== Flash attention on mma.sync tf32 ======================
// FROZEN R11 config (best measured: 463.8us). Do not modify.
#define FBQ 128
#define FQLD 68
#define FVLD 72
#define KS_OFF (FBQ * FQLD)
#define VS_OFF (KS_OFF + 64 * FQLD)
#define PS_OFF (VS_OFF + 64 * FVLD)
#define FSM_FLOATS (PS_OFF + FBQ * FQLD)   // 105472 B

__global__ void __launch_bounds__(128)
flash_mma(const float* __restrict__ Qp, const float* __restrict__ Kp,
          const float* __restrict__ Vp, float* __restrict__ Op) {
    extern __shared__ __align__(16) uint32_t fsm[];
    uint32_t* Qs = fsm;
    uint32_t* Ks = fsm + KS_OFF;
    uint32_t* Vs = fsm + VS_OFF;
    uint32_t* Ps = fsm + PS_OFF;
    const uint32_t sb = smem_u32(fsm);

    const int tid = threadIdx.x;
    const int wid = tid >> 5, lane = tid & 31;
    const int gid = lane >> 2, tg = lane & 3;
    const int q0 = blockIdx.x * FBQ;
    const int h = blockIdx.y, b = blockIdx.z;
    const size_t base = (size_t)b * SS * DD + (size_t)h * DKK;
    const int wm = wid * 32;

#pragma unroll
    for (int t = 0; t < 16; t++) {
        const int i = tid + t * 128;
        const int r = i >> 4, c = (i & 15) * 4;
        cp_async16(sb + (uint32_t)(r * FQLD + c) * 4u,
                   Qp + base + (size_t)(q0 + r) * DD + c);
    }
    CP_COMMIT();

    float m_i[2][2], l_i[2][2];
    float oacc[2][8][4];
#pragma unroll
    for (int mt = 0; mt < 2; mt++) {
        m_i[mt][0] = -1e30f; m_i[mt][1] = -1e30f;
        l_i[mt][0] = 0.0f;   l_i[mt][1] = 0.0f;
#pragma unroll
        for (int nt = 0; nt < 8; nt++)
#pragma unroll
            for (int c = 0; c < 4; c++) oacc[mt][nt][c] = 0.0f;
    }

    for (int kb = 0; kb < SS / 64; kb++) {
        __syncthreads();
#pragma unroll
        for (int t = 0; t < 8; t++) {
            const int i = tid + t * 128;
            const int r = i >> 4, c = (i & 15) * 4;
            cp_async16(sb + (uint32_t)(KS_OFF + r * FQLD + c) * 4u,
                       Kp + base + (size_t)(kb * 64 + r) * DD + c);
        }
        CP_COMMIT();
#pragma unroll
        for (int t = 0; t < 8; t++) {
            const int i = tid + t * 128;
            const int r = i >> 4, c = (i & 15) * 4;
            cp_async16(sb + (uint32_t)(VS_OFF + r * FVLD + c) * 4u,
                       Vp + base + (size_t)(kb * 64 + r) * DD + c);
        }
        CP_COMMIT();
        CP_WAIT(1);
        __syncthreads();

        float s[2][8][4];
#pragma unroll
        for (int mt = 0; mt < 2; mt++)
#pragma unroll
            for (int nt = 0; nt < 8; nt++)
#pragma unroll
                for (int c = 0; c < 4; c++) s[mt][nt][c] = 0.0f;

#pragma unroll
        for (int ks = 0; ks < 8; ks++) {
            const int k0 = ks * 8;
            uint32_t af[2][4], bf[8][2];
#pragma unroll
            for (int mt = 0; mt < 2; mt++) {
                const uint32_t* ap = Qs + (wm + mt * 16 + gid) * FQLD + k0 + tg;
                af[mt][0] = ap[0];
                af[mt][1] = ap[8 * FQLD];
                af[mt][2] = ap[4];
                af[mt][3] = ap[8 * FQLD + 4];
            }
#pragma unroll
            for (int nt = 0; nt < 8; nt++) {
                const uint32_t* bp = Ks + (nt * 8 + gid) * FQLD + k0 + tg;
                bf[nt][0] = bp[0];
                bf[nt][1] = bp[4];
            }
#pragma unroll
            for (int mt = 0; mt < 2; mt++)
#pragma unroll
                for (int nt = 0; nt < 8; nt++)
                    mma_tf32(s[mt][nt], af[mt], bf[nt]);
        }

#pragma unroll
        for (int mt = 0; mt < 2; mt++) {
            float mx0 = -1e30f, mx1 = -1e30f;
#pragma unroll
            for (int nt = 0; nt < 8; nt++) {
                mx0 = fmaxf(mx0, fmaxf(s[mt][nt][0], s[mt][nt][1]));
                mx1 = fmaxf(mx1, fmaxf(s[mt][nt][2], s[mt][nt][3]));
            }
#pragma unroll
            for (int m = 1; m <= 2; m <<= 1) {
                mx0 = fmaxf(mx0, __shfl_xor_sync(0xffffffffu, mx0, m));
                mx1 = fmaxf(mx1, __shfl_xor_sync(0xffffffffu, mx1, m));
            }
            const float mn0 = fmaxf(m_i[mt][0], mx0);
            const float mn1 = fmaxf(m_i[mt][1], mx1);
            const float corr0 = exp2f(m_i[mt][0] - mn0);
            const float corr1 = exp2f(m_i[mt][1] - mn1);
            float sum0 = 0.0f, sum1 = 0.0f;
#pragma unroll
            for (int nt = 0; nt < 8; nt++) {
                s[mt][nt][0] = exp2f(s[mt][nt][0] - mn0);
                s[mt][nt][1] = exp2f(s[mt][nt][1] - mn0);
                s[mt][nt][2] = exp2f(s[mt][nt][2] - mn1);
                s[mt][nt][3] = exp2f(s[mt][nt][3] - mn1);
                sum0 += s[mt][nt][0] + s[mt][nt][1];
                sum1 += s[mt][nt][2] + s[mt][nt][3];
            }
#pragma unroll
            for (int m = 1; m <= 2; m <<= 1) {
                sum0 += __shfl_xor_sync(0xffffffffu, sum0, m);
                sum1 += __shfl_xor_sync(0xffffffffu, sum1, m);
            }
            l_i[mt][0] = l_i[mt][0] * corr0 + sum0;
            l_i[mt][1] = l_i[mt][1] * corr1 + sum1;
            m_i[mt][0] = mn0;
            m_i[mt][1] = mn1;
#pragma unroll
            for (int nt = 0; nt < 8; nt++) {
                oacc[mt][nt][0] *= corr0; oacc[mt][nt][1] *= corr0;
                oacc[mt][nt][2] *= corr1; oacc[mt][nt][3] *= corr1;
            }

#pragma unroll
            for (int nt = 0; nt < 8; nt++) {
                uint32_t* pp = Ps + (wm + mt * 16 + gid) * FQLD + nt * 8 + 2 * tg;
                uint2 lo = make_uint2(f2tf32(s[mt][nt][0]), f2tf32(s[mt][nt][1]));
                uint2 hi = make_uint2(f2tf32(s[mt][nt][2]), f2tf32(s[mt][nt][3]));
                *(uint2*)pp = lo;
                *(uint2*)(pp + 8 * FQLD) = hi;
            }
        }
        __syncwarp();
        CP_WAIT(0);
        __syncthreads();

#pragma unroll
        for (int ks = 0; ks < 8; ks++) {
            const int k0 = ks * 8;
            uint32_t af[2][4], bf[8][2];
#pragma unroll
            for (int mt = 0; mt < 2; mt++) {
                const uint32_t* ap = Ps + (wm + mt * 16 + gid) * FQLD + k0 + tg;
                af[mt][0] = ap[0];
                af[mt][1] = ap[8 * FQLD];
                af[mt][2] = ap[4];
                af[mt][3] = ap[8 * FQLD + 4];
            }
#pragma unroll
            for (int nt = 0; nt < 8; nt++) {
                const uint32_t* bp = Vs + (k0 + tg) * FVLD + nt * 8 + gid;
                bf[nt][0] = bp[0];
                bf[nt][1] = bp[4 * FVLD];
            }
#pragma unroll
            for (int mt = 0; mt < 2; mt++)
#pragma unroll
                for (int nt = 0; nt < 8; nt++)
                    mma_tf32(oacc[mt][nt], af[mt], bf[nt]);
        }
    }

#pragma unroll
    for (int mt = 0; mt < 2; mt++) {
        const float inv0 = 1.0f / l_i[mt][0];
        const float inv1 = 1.0f / l_i[mt][1];
        const int row = q0 + wm + mt * 16 + gid;
#pragma unroll
        for (int nt = 0; nt < 8; nt++) {
            const int col = nt * 8 + 2 * tg;
            uint2 v0 = make_uint2(f2tf32(oacc[mt][nt][0] * inv0),
                                  f2tf32(oacc[mt][nt][1] * inv0));
            uint2 v1 = make_uint2(f2tf32(oacc[mt][nt][2] * inv1),
                                  f2tf32(oacc[mt][nt][3] * inv1));
            *(uint2*)(Op + base + (size_t)row * DD + col) = v0;
            *(uint2*)(Op + base + (size_t)(row + 8) * DD + col) = v1;
        }
    }
}

// ---------------- launch -----------------------------------------------------
extern "C" void kernel_launch(void* const* d_in, const int* in_sizes, int n_in,
                              void* d_out, int out_size) {
    (void)in_sizes; (void)n_in; (void)out_size;
    const float* q  = (const float*)d_in[0];
    const float* k  = (const float*)d_in[1];
    const float* v  = (const float*)d_in[2];
    const float* Wq = (const float*)d_in[3];
    const float* bq = (const float*)d_in[4];
    const float* Wk = (const float*)d_in[5];
    const float* bk = (const float*)d_in[6];
    const float* Wv = (const float*)d_in[7];
    const float* bv = (const float*)d_in[8];
    const float* Wo = (const float*)d_in[9];
    const float* bo = (const float*)d_in[10];
    float* out = (float*)d_out;

    float *qp, *kp, *vp, *ao, *qc, *kc_, *vc, *wT;
    cudaGetSymbolAddress((void**)&qp, g_qp);
    cudaGetSymbolAddress((void**)&kp, g_kp);
    cudaGetSymbolAddress((void**)&vp, g_vp);
    cudaGetSymbolAddress((void**)&ao, g_ao);
    cudaGetSymbolAddress((void**)&qc, g_qc);
    cudaGetSymbolAddress((void**)&kc_, g_kc);
    cudaGetSymbolAddress((void**)&vc, g_vc);
    cudaGetSymbolAddress((void**)&wT, g_wT);
    float* wTo = wT + 3 * (size_t)DD * DD;

    const int gsm_bytes = GSM_FLOATS * 4;   // 110592
    const int fsm_bytes = FSM_FLOATS * 4;   // 105472
    cudaFuncSetAttribute(gemm_qkv, cudaFuncAttributeMaxDynamicSharedMemorySize,
                         gsm_bytes);
    cudaFuncSetAttribute(gemm_mma, cudaFuncAttributeMaxDynamicSharedMemorySize,
                         gsm_bytes);
    cudaFuncSetAttribute(flash_mma, cudaFuncAttributeMaxDynamicSharedMemorySize,
                         fsm_bytes);

    const float qscale = 0.125f * 1.44269504088896340736f;  // 1/sqrt(dk)*log2(e)

    const int nBig = MM * DD / 4;
    dim3 cvt3_grid((nBig + 255) / 256, 1, 3);
    cvt3_tf32<<<cvt3_grid, 256>>>(q, k, v, qc, kc_, vc, nBig);
    dim3 cvt4t_grid(DD / 32, DD / 32, 4);   // (32, 32, 4)
    cvt4t_tf32<<<cvt4t_grid, dim3(32, 8)>>>(Wq, Wk, Wv, Wo, wT);

    dim3 qkv_grid(DD / GTN, MM / GTM, 3);   // (4, 64, 3) = 768 CTAs
    gemm_qkv<<<qkv_grid, 256, gsm_bytes>>>(qc, kc_, vc, wT, bq, bk, bv,
                                           qp, kp, vp, qscale);

    dim3 attn_grid(SS / FBQ, HH, BB);       // (16, 16, 4) = 1024 CTAs
    flash_mma<<<attn_grid, 128, fsm_bytes>>>(qp, kp, vp, ao);

    dim3 gemm_grid(DD / GTN, MM / GTM);     // (4, 64) = 256 CTAs
    gemm_mma<<<gemm_grid, 256, gsm_bytes>>>(ao, wTo, bo, out, 1.0f, 0);
}